// round 14
// baseline (speedup 1.0000x reference)
#include <cuda_runtime.h>
#include <cuda_fp16.h>
#include <cstdint>
#include <math.h>

#define B_      64
#define L_      2048
#define DTS     8
#define DSEQ    120
#define DIN     128
#define H_      64
#define NSPLIT  16
#define TILE_M  128
#define TPB     256
#define NITEMS  (B_ * NSPLIT)    // 1024
#define GRID_P  304              // 2 per SM (152 SMs on GB300)
#define SLOPE   0.2291666666666667f

// smem layout (bytes): header 5KB, X0 (32KB), X1 (32KB)
#define X0_OFF  5120
#define X1_OFF  37888
#define SMEM_TOTAL 70656         // 2 blocks/SM

__device__ float g_m[B_ * NSPLIT];
__device__ float g_s[B_ * NSPLIT];
__device__ float g_acc[B_ * NSPLIT * H_];
__device__ float g_qlast[B_ * H_];
__device__ int   g_cnt[B_];      // zero-init; self-resetting per replay
__device__ int   g_next;         // work ticket; reset by prep each launch
// B-fragment table: [ks 0..7][grp 0..7][lane 0..31] -> uint4 (32 KB)
__device__ uint4 g_Bfrag[8 * 8 * 32];

__device__ __forceinline__ uint32_t smem_u32(const void* p) {
    uint32_t a;
    asm("{ .reg .u64 t; cvta.to.shared.u64 t, %1; cvt.u32.u64 %0, t; }" : "=r"(a) : "l"(p));
    return a;
}
__device__ __forceinline__ float rrelu(float x) { return x >= 0.f ? x : x * SLOPE; }
__device__ __forceinline__ uint32_t cvt_h2(float f0, float f1) {
    __half2 hh = __floats2half2_rn(f0, f1);
    return *reinterpret_cast<uint32_t*>(&hh);
}

#define LDSM_X4(r0, r1, r2, r3, addr) \
    asm volatile("ldmatrix.sync.aligned.m8n8.x4.shared.b16 {%0,%1,%2,%3}, [%4];" \
        : "=r"(r0), "=r"(r1), "=r"(r2), "=r"(r3) : "r"(addr))

__device__ __forceinline__ void mma_f16(float (&c)[4], uint32_t a0, uint32_t a1,
                                        uint32_t a2, uint32_t a3,
                                        uint32_t b0, uint32_t b1) {
    asm volatile(
        "mma.sync.aligned.m16n8k16.row.col.f32.f16.f16.f32 "
        "{%0,%1,%2,%3}, {%4,%5,%6,%7}, {%8,%9}, {%0,%1,%2,%3};"
        : "+f"(c[0]), "+f"(c[1]), "+f"(c[2]), "+f"(c[3])
        : "r"(a0), "r"(a1), "r"(a2), "r"(a3), "r"(b0), "r"(b1));
}

// ---------------------------------------------------------------------------
// prep: block 0 also resets the work ticket. Blocks 0-7 build the B-fragment
// table; blocks 8-71 compute q_last[b].
// ---------------------------------------------------------------------------
__global__ void __launch_bounds__(TPB, 2)
prep_kernel(const float* __restrict__ ts, const float* __restrict__ seq,
            const int* __restrict__ lengths,
            const float* __restrict__ Wk, const float* __restrict__ Wv,
            const float* __restrict__ Wq, const float* __restrict__ bq) {
    int tid = threadIdx.x;
    if (blockIdx.x == 0 && tid == 0) g_next = 0;
    if (blockIdx.x < 8) {
        int wid = tid >> 5, lane = tid & 31;
        int wg = blockIdx.x * 8 + wid;        // 0..63
        int ks = wg >> 3, grp = wg & 7;
        int t = lane & 3, g = lane >> 2;
        int k0 = ks * 16 + 2 * t;
        int c = grp * 16 + g;
        const float* W0 = (c < H_) ? (Wk + c) : (Wv + c - H_);
        const float* W1 = (c + 8 < H_) ? (Wk + c + 8) : (Wv + c + 8 - H_);
        uint4 f;
        f.x = cvt_h2(W0[k0 * H_],       W0[(k0 + 1) * H_]);
        f.y = cvt_h2(W0[(k0 + 8) * H_], W0[(k0 + 9) * H_]);
        f.z = cvt_h2(W1[k0 * H_],       W1[(k0 + 1) * H_]);
        f.w = cvt_h2(W1[(k0 + 8) * H_], W1[(k0 + 9) * H_]);
        g_Bfrag[wg * 32 + lane] = f;
    } else {
        int b = blockIdx.x - 8;
        __shared__ float sXlast[DIN];
        __shared__ float sQpart[256];
        int len = lengths[b];
        if (tid < DIN) {
            int l = len - 1;
            sXlast[tid] = (tid < DTS) ? ts[((size_t)b * L_ + l) * DTS + tid]
                                      : seq[((size_t)b * L_ + l) * DSEQ + (tid - DTS)];
        }
        __syncthreads();
        {
            int h = tid & 63, part = tid >> 6;
            float s = 0.f;
            const float* wq = Wq + part * 32 * H_ + h;
#pragma unroll 8
            for (int d = 0; d < 32; ++d) s += sXlast[part * 32 + d] * wq[d * H_];
            sQpart[part * 64 + h] = s;
        }
        __syncthreads();
        if (tid < H_) {
            float s = sQpart[tid] + sQpart[64 + tid] + sQpart[128 + tid] + sQpart[192 + tid];
            g_qlast[b * H_ + tid] = rrelu(s + bq[tid]);
        }
    }
}

// X tile fill: fp32 -> fp16, swizzled, into buffer at bufoff
__device__ __forceinline__ void fill_x(char* smem, int bufoff,
                                       const float* __restrict__ ts,
                                       const float* __restrict__ seq,
                                       int b, int start, int tid) {
#pragma unroll
    for (int it = 0; it < 8; ++it) {
        int j = tid + it * TPB;               // 0..2047
        int row = j >> 4, ch = j & 15;
        int token = start + row;
        const float* src = (ch == 0)
            ? (ts + ((size_t)b * L_ + token) * DTS)
            : (seq + ((size_t)b * L_ + token) * DSEQ + (ch * 8 - 8));
        float4 f0 = ((const float4*)src)[0];
        float4 f1 = ((const float4*)src)[1];
        uint4 v = make_uint4(cvt_h2(f0.x, f0.y), cvt_h2(f0.z, f0.w),
                             cvt_h2(f1.x, f1.y), cvt_h2(f1.z, f1.w));
        uint32_t off = (uint32_t)(row * 256 + ((ch ^ (row & 7)) << 4));
        *(uint4*)(smem + bufoff + off) = v;
    }
}

// ---------------------------------------------------------------------------
// fused persistent kernel: 304 blocks pull items (b, sp) from a global ticket.
// Double-buffered X: fill for item k+1 issued before compute of item k.
// Compute body = R12 (K/V warp split, B from fragment table).
// ---------------------------------------------------------------------------
__global__ void __launch_bounds__(TPB, 2)
fused_attn(const float* __restrict__ ts, const float* __restrict__ seq,
           const int* __restrict__ lengths,
           const float* __restrict__ bk, const float* __restrict__ bv,
           float* __restrict__ out) {
    int tid = threadIdx.x;
    int wid = tid >> 5, lane = tid & 31;

    extern __shared__ char smem[];
    uint32_t sb = smem_u32(smem);
    float* sBias  = (float*)(smem + 256);     // 128
    float* sScore = (float*)(smem + 768);     // 128
    float* sRed   = (float*)(smem + 1280);    // 256
    int*   sLast  = (int*)(smem + 2304);
    int*   sJ     = (int*)(smem + 2312);
    int*   sLen   = (int*)(smem + 2560);      // 64
    float* sQb    = (float*)(smem + 2816);    // 2 x 64

    if (tid < DIN) sBias[tid] = (tid < H_) ? bk[tid] : bv[tid - H_];
    if (tid < B_)  sLen[tid] = lengths[tid];
    __syncthreads();

    // block-uniform live-item acquire
    auto acquire = [&]() -> int {
        while (true) {
            if (tid == 0) *sJ = atomicAdd(&g_next, 1);
            __syncthreads();
            int jj = *sJ;
            __syncthreads();
            if (jj >= NITEMS) return -1;
            if (((jj & 15) << 7) < sLen[jj >> 4]) return jj;
        }
    };

    int li = lane >> 3, lr = lane & 7;
    int roff = ((li & 1) << 3) + lr;
    int ci   = li >> 1;
    int rm   = roff & 7;
    int g = lane >> 2, t = lane & 3;
    int t2 = 2 * t;
    int kw = wid & 3;
    int isV = wid >> 2;
    const uint4* bf = g_Bfrag + (isV * 4) * 32 + lane;

    int j = acquire();
    if (j < 0) return;
    int cur = 0;
    {
        int b = j >> 4, start = (j & 15) << 7;
        fill_x(smem, X0_OFF, ts, seq, b, start, tid);
        if (tid < H_) sQb[tid] = g_qlast[b * H_ + tid];
    }

    while (j >= 0) {
        __syncthreads();                      // fill(cur) + sQb(cur) visible

        int jn = acquire();
        if (jn >= 0) {                        // prefetch next item's X
            int bn = jn >> 4, sn = (jn & 15) << 7;
            fill_x(smem, cur ? X0_OFF : X1_OFF, ts, seq, bn, sn, tid);
            if (tid < H_) sQb[(cur ^ 1) * H_ + tid] = g_qlast[bn * H_ + tid];
        }

        // ================= compute item j on buffer cur =================
        int b   = j >> 4;
        int sp  = j & 15;
        int len = sLen[b];
        int start = sp << 7;
        int idx = b * NSPLIT + sp;
        int nlive = min(NSPLIT, (len + TILE_M - 1) >> 7);
        float* sQ = sQb + cur * H_;

        uint32_t a_row0 = sb + (cur ? X1_OFF : X0_OFF)
                        + (uint32_t)((kw * 32 + roff) * 256);
        uint32_t a_row1 = a_row0 + 16 * 256;

        float acc[2][8][4];
#pragma unroll
        for (int ms = 0; ms < 2; ++ms)
#pragma unroll
            for (int n = 0; n < 8; ++n)
#pragma unroll
                for (int i = 0; i < 4; ++i) acc[ms][n][i] = 0.f;

#pragma unroll
        for (int ks = 0; ks < 8; ++ks) {
            uint32_t aoff = ((uint32_t)((2 * ks + ci) ^ rm)) << 4;
            uint32_t a00, a01, a02, a03, a10, a11, a12, a13;
            LDSM_X4(a00, a01, a02, a03, a_row0 + aoff);
            LDSM_X4(a10, a11, a12, a13, a_row1 + aoff);
#pragma unroll
            for (int ntp = 0; ntp < 4; ++ntp) {
                uint4 f = bf[(ks * 8 + ntp) * 32];
                mma_f16(acc[0][2 * ntp],     a00, a01, a02, a03, f.x, f.y);
                mma_f16(acc[0][2 * ntp + 1], a00, a01, a02, a03, f.z, f.w);
                mma_f16(acc[1][2 * ntp],     a10, a11, a12, a13, f.x, f.y);
                mma_f16(acc[1][2 * ntp + 1], a10, a11, a12, a13, f.z, f.w);
            }
        }

        // ---- K warps: scores ----
        if (!isV) {
#pragma unroll
            for (int ms = 0; ms < 2; ++ms) {
                float s0 = 0.f, s1 = 0.f;
#pragma unroll
                for (int nt = 0; nt < 8; ++nt) {
                    int c0 = 8 * nt + t2, c1 = c0 + 1;
                    float q0 = sQ[c0], q1 = sQ[c1];
                    float b0 = sBias[c0], b1 = sBias[c1];
                    s0 += q0 * rrelu(acc[ms][nt][0] + b0) + q1 * rrelu(acc[ms][nt][1] + b1);
                    s1 += q0 * rrelu(acc[ms][nt][2] + b0) + q1 * rrelu(acc[ms][nt][3] + b1);
                }
                s0 += __shfl_xor_sync(0xffffffffu, s0, 1);
                s0 += __shfl_xor_sync(0xffffffffu, s0, 2);
                s1 += __shfl_xor_sync(0xffffffffu, s1, 1);
                s1 += __shfl_xor_sync(0xffffffffu, s1, 2);
                if (t == 0) {
                    int r0 = kw * 32 + ms * 16 + g, r1 = r0 + 8;
                    sScore[r0] = (start + r0 < len) ? s0 : -INFINITY;
                    sScore[r1] = (start + r1 < len) ? s1 : -INFINITY;
                }
            }
        }
        __syncthreads();

        // ---- all-warp redundant softmax ----
        float mx, sum;
        {
            float v0 = sScore[lane], v1 = sScore[lane + 32];
            float v2 = sScore[lane + 64], v3 = sScore[lane + 96];
            mx = fmaxf(fmaxf(v0, v1), fmaxf(v2, v3));
#pragma unroll
            for (int o = 16; o >= 1; o >>= 1)
                mx = fmaxf(mx, __shfl_xor_sync(0xffffffffu, mx, o));
            sum = __expf(v0 - mx) + __expf(v1 - mx)
                + __expf(v2 - mx) + __expf(v3 - mx);
#pragma unroll
            for (int o = 16; o >= 1; o >>= 1)
                sum += __shfl_xor_sync(0xffffffffu, sum, o);
        }

        // ---- V warps: weighted accumulate ----
        if (isV) {
            int rb = kw * 32;
            float wa = __expf(sScore[rb + g]      - mx);
            float wb = __expf(sScore[rb + g + 8]  - mx);
            float wc = __expf(sScore[rb + g + 16] - mx);
            float wd = __expf(sScore[rb + g + 24] - mx);
#pragma unroll
            for (int nt = 0; nt < 8; ++nt) {
                int c0 = 8 * nt + t2, c1 = c0 + 1;
                float b0 = sBias[64 + c0], b1 = sBias[64 + c1];
                float p0 = wa * rrelu(acc[0][nt][0] + b0) + wb * rrelu(acc[0][nt][2] + b0)
                         + wc * rrelu(acc[1][nt][0] + b0) + wd * rrelu(acc[1][nt][2] + b0);
                float p1 = wa * rrelu(acc[0][nt][1] + b1) + wb * rrelu(acc[0][nt][3] + b1)
                         + wc * rrelu(acc[1][nt][1] + b1) + wd * rrelu(acc[1][nt][3] + b1);
                p0 += __shfl_xor_sync(0xffffffffu, p0, 4);
                p0 += __shfl_xor_sync(0xffffffffu, p0, 8);
                p0 += __shfl_xor_sync(0xffffffffu, p0, 16);
                p1 += __shfl_xor_sync(0xffffffffu, p1, 4);
                p1 += __shfl_xor_sync(0xffffffffu, p1, 8);
                p1 += __shfl_xor_sync(0xffffffffu, p1, 16);
                if (g == 0) {
                    sRed[kw * 64 + c0] = p0;
                    sRed[kw * 64 + c1] = p1;
                }
            }
        }
        __syncthreads();

        // ---- per-split partials ----
        if (tid < H_) {
            g_acc[idx * H_ + tid] = sRed[tid] + sRed[64 + tid]
                                  + sRed[128 + tid] + sRed[192 + tid];
        }
        if (tid == 0) { g_m[idx] = mx; g_s[idx] = sum; }

        // ---- last-block combine (threadfence reduction) ----
        __threadfence();
        __syncthreads();
        if (tid == 0) {
            int old = atomicAdd(&g_cnt[b], 1);
            *sLast = (old == nlive - 1);
        }
        __syncthreads();
        if (*sLast) {
            if (tid < H_) {
                volatile float* vm = g_m + b * NSPLIT;
                volatile float* vs = g_s + b * NSPLIT;
                volatile float* va = g_acc + (size_t)b * NSPLIT * H_;
                float MM = -INFINITY;
                for (int i = 0; i < nlive; ++i) MM = fmaxf(MM, vm[i]);
                float S = 0.f, A = 0.f;
                for (int i = 0; i < nlive; ++i) {
                    float e = __expf(vm[i] - MM);
                    S += vs[i] * e;
                    A += va[i * H_ + tid] * e;
                }
                out[b * H_ + tid] = A / S;
            }
            if (tid == 0) g_cnt[b] = 0;   // reset for next replay
        }

        j = jn;
        cur ^= 1;
    }
}

// ---------------------------------------------------------------------------
extern "C" void kernel_launch(void* const* d_in, const int* in_sizes, int n_in,
                              void* d_out, int out_size) {
    const float* ts      = (const float*)d_in[0];
    const float* seq     = (const float*)d_in[1];
    const int*   lengths = (const int*)  d_in[2];
    const float* Wk      = (const float*)d_in[3];
    const float* bk      = (const float*)d_in[4];
    const float* Wq      = (const float*)d_in[5];
    const float* bq      = (const float*)d_in[6];
    const float* Wv      = (const float*)d_in[7];
    const float* bv      = (const float*)d_in[8];
    float* out = (float*)d_out;

    static int configured = 0;
    if (!configured) {
        cudaFuncSetAttribute(fused_attn,
                             cudaFuncAttributeMaxDynamicSharedMemorySize, SMEM_TOTAL);
        configured = 1;
    }

    prep_kernel<<<8 + B_, TPB>>>(ts, seq, lengths, Wk, Wv, Wq, bq);
    fused_attn<<<GRID_P, TPB, SMEM_TOTAL>>>(ts, seq, lengths, bk, bv, out);
}

// round 15
// speedup vs baseline: 1.0370x; 1.0370x over previous
#include <cuda_runtime.h>
#include <cuda_fp16.h>
#include <cstdint>
#include <math.h>

#define B_      64
#define L_      2048
#define DTS     8
#define DSEQ    120
#define DIN     128
#define H_      64
#define NSPLIT  16
#define TILE_M  128              // tokens per block
#define TPB     256
#define SLOPE   0.2291666666666667f

// smem layout (bytes): header 5KB, X fp32 staging (64KB), X fp16 tile (32KB)
#define X32_OFF 5120
#define XH_OFF  70656
#define SMEM_TOTAL 103424        // 2 blocks/SM

__device__ float g_m[B_ * NSPLIT];
__device__ float g_s[B_ * NSPLIT];
__device__ float g_acc[B_ * NSPLIT * H_];
__device__ float g_qlast[B_ * H_];
__device__ int   g_cnt[B_];      // zero-init; self-resetting per replay
// B-fragment table: [ks 0..7][grp 0..7][lane 0..31] -> uint4 (32 KB)
__device__ uint4 g_Bfrag[8 * 8 * 32];

__device__ __forceinline__ uint32_t smem_u32(const void* p) {
    uint32_t a;
    asm("{ .reg .u64 t; cvta.to.shared.u64 t, %1; cvt.u32.u64 %0, t; }" : "=r"(a) : "l"(p));
    return a;
}
__device__ __forceinline__ float rrelu(float x) { return x >= 0.f ? x : x * SLOPE; }
__device__ __forceinline__ uint32_t cvt_h2(float f0, float f1) {
    __half2 hh = __floats2half2_rn(f0, f1);
    return *reinterpret_cast<uint32_t*>(&hh);
}

#define CP_ASYNC16(dst, src) \
    asm volatile("cp.async.ca.shared.global [%0], [%1], 16;" \
        :: "r"(dst), "l"(src) : "memory")
#define CP_COMMIT()  asm volatile("cp.async.commit_group;" ::: "memory")
#define CP_WAIT0()   asm volatile("cp.async.wait_group 0;" ::: "memory")

#define LDSM_X4(r0, r1, r2, r3, addr) \
    asm volatile("ldmatrix.sync.aligned.m8n8.x4.shared.b16 {%0,%1,%2,%3}, [%4];" \
        : "=r"(r0), "=r"(r1), "=r"(r2), "=r"(r3) : "r"(addr))

__device__ __forceinline__ void mma_f16(float (&c)[4], uint32_t a0, uint32_t a1,
                                        uint32_t a2, uint32_t a3,
                                        uint32_t b0, uint32_t b1) {
    asm volatile(
        "mma.sync.aligned.m16n8k16.row.col.f32.f16.f16.f32 "
        "{%0,%1,%2,%3}, {%4,%5,%6,%7}, {%8,%9}, {%0,%1,%2,%3};"
        : "+f"(c[0]), "+f"(c[1]), "+f"(c[2]), "+f"(c[3])
        : "r"(a0), "r"(a1), "r"(a2), "r"(a3), "r"(b0), "r"(b1));
}

// ---------------------------------------------------------------------------
// prep: blocks 0-7 build the B-fragment table; blocks 8-71 compute q_last[b].
// ---------------------------------------------------------------------------
__global__ void __launch_bounds__(TPB, 2)
prep_kernel(const float* __restrict__ ts, const float* __restrict__ seq,
            const int* __restrict__ lengths,
            const float* __restrict__ Wk, const float* __restrict__ Wv,
            const float* __restrict__ Wq, const float* __restrict__ bq) {
    int tid = threadIdx.x;
    if (blockIdx.x < 8) {
        int wid = tid >> 5, lane = tid & 31;
        int wg = blockIdx.x * 8 + wid;        // 0..63
        int ks = wg >> 3, grp = wg & 7;
        int t = lane & 3, g = lane >> 2;
        int k0 = ks * 16 + 2 * t;
        int c = grp * 16 + g;
        const float* W0 = (c < H_) ? (Wk + c) : (Wv + c - H_);
        const float* W1 = (c + 8 < H_) ? (Wk + c + 8) : (Wv + c + 8 - H_);
        uint4 f;
        f.x = cvt_h2(W0[k0 * H_],       W0[(k0 + 1) * H_]);
        f.y = cvt_h2(W0[(k0 + 8) * H_], W0[(k0 + 9) * H_]);
        f.z = cvt_h2(W1[k0 * H_],       W1[(k0 + 1) * H_]);
        f.w = cvt_h2(W1[(k0 + 8) * H_], W1[(k0 + 9) * H_]);
        g_Bfrag[wg * 32 + lane] = f;
    } else {
        int b = blockIdx.x - 8;
        __shared__ float sXlast[DIN];
        __shared__ float sQpart[256];
        int len = lengths[b];
        if (tid < DIN) {
            int l = len - 1;
            sXlast[tid] = (tid < DTS) ? ts[((size_t)b * L_ + l) * DTS + tid]
                                      : seq[((size_t)b * L_ + l) * DSEQ + (tid - DTS)];
        }
        __syncthreads();
        {
            int h = tid & 63, part = tid >> 6;
            float s = 0.f;
            const float* wq = Wq + part * 32 * H_ + h;
#pragma unroll 8
            for (int d = 0; d < 32; ++d) s += sXlast[part * 32 + d] * wq[d * H_];
            sQpart[part * 64 + h] = s;
        }
        __syncthreads();
        if (tid < H_) {
            float s = sQpart[tid] + sQpart[64 + tid] + sQpart[128 + tid] + sQpart[192 + tid];
            g_qlast[b * H_ + tid] = rrelu(s + bq[tid]);
        }
    }
}

// ---------------------------------------------------------------------------
// fused: per (split, batch) block — ONE 128-token tile.
// X loaded via cp.async into fp32 staging (register-free, unbounded MLP),
// then converted smem->smem to the swizzled fp16 tile. GEMM body = R12.
// ---------------------------------------------------------------------------
__global__ void __launch_bounds__(TPB, 2)
fused_attn(const float* __restrict__ ts, const float* __restrict__ seq,
           const int* __restrict__ lengths,
           const float* __restrict__ bk, const float* __restrict__ bv,
           float* __restrict__ out) {
    int b   = blockIdx.y;
    int sp  = blockIdx.x;
    int len = lengths[b];
    int start = sp * TILE_M;
    int tid = threadIdx.x;
    int wid = tid >> 5, lane = tid & 31;
    int idx = b * NSPLIT + sp;
    int nlive = min(NSPLIT, (len + TILE_M - 1) >> 7);

    if (sp >= nlive) return;   // dead split

    extern __shared__ char smem[];
    uint32_t sb = smem_u32(smem);
    float* sQ      = (float*)smem;             // 64
    float* sBias   = (float*)(smem + 256);     // 128
    float* sScore  = (float*)(smem + 768);     // 128
    float* sRed    = (float*)(smem + 1280);    // 256
    int*   sLast   = (int*)(smem + 2304);

    // ---- X tile: cp.async fp32 -> staging (4096 x 16B), fully async ----
    {
        uint32_t stage = sb + X32_OFF;
#pragma unroll
        for (int it = 0; it < 16; ++it) {
            int j = tid + it * TPB;           // 0..4095
            int row = j >> 5, ch = j & 31;    // 32 x 16B chunks per 512B row
            int token = start + row;
            const float* src = (ch < 2)
                ? (ts + ((size_t)b * L_ + token) * DTS + ch * 4)
                : (seq + ((size_t)b * L_ + token) * DSEQ + (ch - 2) * 4);
            CP_ASYNC16(stage + (uint32_t)(row * 512 + ch * 16), src);
        }
        CP_COMMIT();
    }

    // ---- header loads overlap the async copies ----
    if (tid < DIN) sBias[tid] = (tid < H_) ? bk[tid] : bv[tid - H_];
    if (tid < H_)  sQ[tid] = g_qlast[b * H_ + tid];

    CP_WAIT0();
    __syncthreads();

    // ---- convert staging fp32 -> swizzled fp16 tile (pure smem pass) ----
#pragma unroll
    for (int it = 0; it < 8; ++it) {
        int j = tid + it * TPB;               // 0..2047
        int row = j >> 4, ch = j & 15;
        const float4* s4 = (const float4*)(smem + X32_OFF + row * 512 + ch * 32);
        float4 f0 = s4[0];
        float4 f1 = s4[1];
        uint4 v = make_uint4(cvt_h2(f0.x, f0.y), cvt_h2(f0.z, f0.w),
                             cvt_h2(f1.x, f1.y), cvt_h2(f1.z, f1.w));
        uint32_t off = (uint32_t)(row * 256 + ((ch ^ (row & 7)) << 4));
        *(uint4*)(smem + XH_OFF + off) = v;
    }
    __syncthreads();

    int kw = wid & 3;                 // row group
    int isV = wid >> 2;               // 0 = K cols (0-63), 1 = V cols (64-127)

    int li = lane >> 3, lr = lane & 7;
    int roff = ((li & 1) << 3) + lr;
    int ci   = li >> 1;
    int rm   = roff & 7;
    int g = lane >> 2, t = lane & 3;
    int t2 = 2 * t;

    const uint4* bf = g_Bfrag + (isV * 4) * 32 + lane;

    uint32_t a_row0 = sb + XH_OFF + (uint32_t)((kw * 32 + roff) * 256);
    uint32_t a_row1 = a_row0 + 16 * 256;

    float acc[2][8][4];
#pragma unroll
    for (int ms = 0; ms < 2; ++ms)
#pragma unroll
        for (int n = 0; n < 8; ++n)
#pragma unroll
            for (int i = 0; i < 4; ++i) acc[ms][n][i] = 0.f;

#pragma unroll
    for (int ks = 0; ks < 8; ++ks) {
        uint32_t aoff = ((uint32_t)((2 * ks + ci) ^ rm)) << 4;
        uint32_t a00, a01, a02, a03, a10, a11, a12, a13;
        LDSM_X4(a00, a01, a02, a03, a_row0 + aoff);
        LDSM_X4(a10, a11, a12, a13, a_row1 + aoff);
#pragma unroll
        for (int ntp = 0; ntp < 4; ++ntp) {
            uint4 f = bf[(ks * 8 + ntp) * 32];
            mma_f16(acc[0][2 * ntp],     a00, a01, a02, a03, f.x, f.y);
            mma_f16(acc[0][2 * ntp + 1], a00, a01, a02, a03, f.z, f.w);
            mma_f16(acc[1][2 * ntp],     a10, a11, a12, a13, f.x, f.y);
            mma_f16(acc[1][2 * ntp + 1], a10, a11, a12, a13, f.z, f.w);
        }
    }

    // ---- K warps: scores ----
    if (!isV) {
#pragma unroll
        for (int ms = 0; ms < 2; ++ms) {
            float s0 = 0.f, s1 = 0.f;
#pragma unroll
            for (int nt = 0; nt < 8; ++nt) {
                int c0 = 8 * nt + t2, c1 = c0 + 1;
                float q0 = sQ[c0], q1 = sQ[c1];
                float b0 = sBias[c0], b1 = sBias[c1];
                s0 += q0 * rrelu(acc[ms][nt][0] + b0) + q1 * rrelu(acc[ms][nt][1] + b1);
                s1 += q0 * rrelu(acc[ms][nt][2] + b0) + q1 * rrelu(acc[ms][nt][3] + b1);
            }
            s0 += __shfl_xor_sync(0xffffffffu, s0, 1);
            s0 += __shfl_xor_sync(0xffffffffu, s0, 2);
            s1 += __shfl_xor_sync(0xffffffffu, s1, 1);
            s1 += __shfl_xor_sync(0xffffffffu, s1, 2);
            if (t == 0) {
                int r0 = kw * 32 + ms * 16 + g, r1 = r0 + 8;
                sScore[r0] = (start + r0 < len) ? s0 : -INFINITY;
                sScore[r1] = (start + r1 < len) ? s1 : -INFINITY;
            }
        }
    }
    __syncthreads();

    // ---- all-warp redundant softmax ----
    float mx, sum;
    {
        float v0 = sScore[lane], v1 = sScore[lane + 32];
        float v2 = sScore[lane + 64], v3 = sScore[lane + 96];
        mx = fmaxf(fmaxf(v0, v1), fmaxf(v2, v3));
#pragma unroll
        for (int o = 16; o >= 1; o >>= 1)
            mx = fmaxf(mx, __shfl_xor_sync(0xffffffffu, mx, o));
        sum = __expf(v0 - mx) + __expf(v1 - mx)
            + __expf(v2 - mx) + __expf(v3 - mx);
#pragma unroll
        for (int o = 16; o >= 1; o >>= 1)
            sum += __shfl_xor_sync(0xffffffffu, sum, o);
    }

    // ---- V warps: weighted accumulate ----
    if (isV) {
        int rb = kw * 32;
        float wa = __expf(sScore[rb + g]      - mx);
        float wb = __expf(sScore[rb + g + 8]  - mx);
        float wc = __expf(sScore[rb + g + 16] - mx);
        float wd = __expf(sScore[rb + g + 24] - mx);
#pragma unroll
        for (int nt = 0; nt < 8; ++nt) {
            int c0 = 8 * nt + t2, c1 = c0 + 1;
            float b0 = sBias[64 + c0], b1 = sBias[64 + c1];
            float p0 = wa * rrelu(acc[0][nt][0] + b0) + wb * rrelu(acc[0][nt][2] + b0)
                     + wc * rrelu(acc[1][nt][0] + b0) + wd * rrelu(acc[1][nt][2] + b0);
            float p1 = wa * rrelu(acc[0][nt][1] + b1) + wb * rrelu(acc[0][nt][3] + b1)
                     + wc * rrelu(acc[1][nt][1] + b1) + wd * rrelu(acc[1][nt][3] + b1);
            p0 += __shfl_xor_sync(0xffffffffu, p0, 4);
            p0 += __shfl_xor_sync(0xffffffffu, p0, 8);
            p0 += __shfl_xor_sync(0xffffffffu, p0, 16);
            p1 += __shfl_xor_sync(0xffffffffu, p1, 4);
            p1 += __shfl_xor_sync(0xffffffffu, p1, 8);
            p1 += __shfl_xor_sync(0xffffffffu, p1, 16);
            if (g == 0) {
                sRed[kw * 64 + c0] = p0;
                sRed[kw * 64 + c1] = p1;
            }
        }
    }
    __syncthreads();

    // ---- per-split partials ----
    if (tid < H_) {
        g_acc[idx * H_ + tid] = sRed[tid] + sRed[64 + tid]
                              + sRed[128 + tid] + sRed[192 + tid];
    }
    if (tid == 0) { g_m[idx] = mx; g_s[idx] = sum; }

    // ---- last-block combine (threadfence reduction) ----
    __threadfence();
    __syncthreads();
    if (tid == 0) {
        int old = atomicAdd(&g_cnt[b], 1);
        *sLast = (old == nlive - 1);
    }
    __syncthreads();
    if (*sLast) {
        if (tid < H_) {
            volatile float* vm = g_m + b * NSPLIT;
            volatile float* vs = g_s + b * NSPLIT;
            volatile float* va = g_acc + (size_t)b * NSPLIT * H_;
            float MM = -INFINITY;
            for (int i = 0; i < nlive; ++i) MM = fmaxf(MM, vm[i]);
            float S = 0.f, A = 0.f;
            for (int i = 0; i < nlive; ++i) {
                float e = __expf(vm[i] - MM);
                S += vs[i] * e;
                A += va[i * H_ + tid] * e;
            }
            out[b * H_ + tid] = A / S;
        }
        if (tid == 0) g_cnt[b] = 0;   // reset for next replay
    }
}

// ---------------------------------------------------------------------------
extern "C" void kernel_launch(void* const* d_in, const int* in_sizes, int n_in,
                              void* d_out, int out_size) {
    const float* ts      = (const float*)d_in[0];
    const float* seq     = (const float*)d_in[1];
    const int*   lengths = (const int*)  d_in[2];
    const float* Wk      = (const float*)d_in[3];
    const float* bk      = (const float*)d_in[4];
    const float* Wq      = (const float*)d_in[5];
    const float* bq      = (const float*)d_in[6];
    const float* Wv      = (const float*)d_in[7];
    const float* bv      = (const float*)d_in[8];
    float* out = (float*)d_out;

    static int configured = 0;
    if (!configured) {
        cudaFuncSetAttribute(fused_attn,
                             cudaFuncAttributeMaxDynamicSharedMemorySize, SMEM_TOTAL);
        configured = 1;
    }

    prep_kernel<<<8 + B_, TPB>>>(ts, seq, lengths, Wk, Wv, Wq, bq);
    dim3 grid(NSPLIT, B_);
    fused_attn<<<grid, TPB, SMEM_TOTAL>>>(ts, seq, lengths, bk, bv, out);
}

// round 16
// speedup vs baseline: 1.2171x; 1.1737x over previous
#include <cuda_runtime.h>
#include <cuda_fp16.h>
#include <cstdint>
#include <math.h>

#define B_      64
#define L_      2048
#define DTS     8
#define DSEQ    120
#define DIN     128
#define H_      64
#define NSPLIT  32
#define TILE_M  64               // tokens per block
#define TPB     128
#define SLOPE   0.2291666666666667f

// smem layout (bytes): header 2.5KB, X (16KB)
#define XH_OFF  2560
#define SMEM_TOTAL 18944         // 4 blocks/SM

__device__ float g_m[B_ * NSPLIT];
__device__ float g_s[B_ * NSPLIT];
__device__ float g_acc[B_ * NSPLIT * H_];
__device__ float g_qlast[B_ * H_];
__device__ int   g_cnt[B_];      // zero-init; self-resetting per replay
// B-fragment table: [ks 0..7][grp 0..7][lane 0..31] -> uint4 (32 KB)
__device__ uint4 g_Bfrag[8 * 8 * 32];

__device__ __forceinline__ uint32_t smem_u32(const void* p) {
    uint32_t a;
    asm("{ .reg .u64 t; cvta.to.shared.u64 t, %1; cvt.u32.u64 %0, t; }" : "=r"(a) : "l"(p));
    return a;
}
__device__ __forceinline__ float rrelu(float x) { return x >= 0.f ? x : x * SLOPE; }
__device__ __forceinline__ uint32_t cvt_h2(float f0, float f1) {
    __half2 hh = __floats2half2_rn(f0, f1);
    return *reinterpret_cast<uint32_t*>(&hh);
}

#define LDSM_X4(r0, r1, r2, r3, addr) \
    asm volatile("ldmatrix.sync.aligned.m8n8.x4.shared.b16 {%0,%1,%2,%3}, [%4];" \
        : "=r"(r0), "=r"(r1), "=r"(r2), "=r"(r3) : "r"(addr))

__device__ __forceinline__ void mma_f16(float (&c)[4], uint32_t a0, uint32_t a1,
                                        uint32_t a2, uint32_t a3,
                                        uint32_t b0, uint32_t b1) {
    asm volatile(
        "mma.sync.aligned.m16n8k16.row.col.f32.f16.f16.f32 "
        "{%0,%1,%2,%3}, {%4,%5,%6,%7}, {%8,%9}, {%0,%1,%2,%3};"
        : "+f"(c[0]), "+f"(c[1]), "+f"(c[2]), "+f"(c[3])
        : "r"(a0), "r"(a1), "r"(a2), "r"(a3), "r"(b0), "r"(b1));
}

// ---------------------------------------------------------------------------
// prep: blocks 0-7 build the B-fragment table; blocks 8-71 compute q_last[b].
// ---------------------------------------------------------------------------
__global__ void __launch_bounds__(256, 2)
prep_kernel(const float* __restrict__ ts, const float* __restrict__ seq,
            const int* __restrict__ lengths,
            const float* __restrict__ Wk, const float* __restrict__ Wv,
            const float* __restrict__ Wq, const float* __restrict__ bq) {
    int tid = threadIdx.x;
    if (blockIdx.x < 8) {
        int wid = tid >> 5, lane = tid & 31;
        int wg = blockIdx.x * 8 + wid;        // 0..63
        int ks = wg >> 3, grp = wg & 7;
        int t = lane & 3, g = lane >> 2;
        int k0 = ks * 16 + 2 * t;
        int c = grp * 16 + g;
        const float* W0 = (c < H_) ? (Wk + c) : (Wv + c - H_);
        const float* W1 = (c + 8 < H_) ? (Wk + c + 8) : (Wv + c + 8 - H_);
        uint4 f;
        f.x = cvt_h2(W0[k0 * H_],       W0[(k0 + 1) * H_]);
        f.y = cvt_h2(W0[(k0 + 8) * H_], W0[(k0 + 9) * H_]);
        f.z = cvt_h2(W1[k0 * H_],       W1[(k0 + 1) * H_]);
        f.w = cvt_h2(W1[(k0 + 8) * H_], W1[(k0 + 9) * H_]);
        g_Bfrag[wg * 32 + lane] = f;
    } else {
        int b = blockIdx.x - 8;
        __shared__ float sXlast[DIN];
        __shared__ float sQpart[256];
        int len = lengths[b];
        if (tid < DIN) {
            int l = len - 1;
            sXlast[tid] = (tid < DTS) ? ts[((size_t)b * L_ + l) * DTS + tid]
                                      : seq[((size_t)b * L_ + l) * DSEQ + (tid - DTS)];
        }
        __syncthreads();
        {
            int h = tid & 63, part = tid >> 6;
            float s = 0.f;
            const float* wq = Wq + part * 32 * H_ + h;
#pragma unroll 8
            for (int d = 0; d < 32; ++d) s += sXlast[part * 32 + d] * wq[d * H_];
            sQpart[part * 64 + h] = s;
        }
        __syncthreads();
        if (tid < H_) {
            float s = sQpart[tid] + sQpart[64 + tid] + sQpart[128 + tid] + sQpart[192 + tid];
            g_qlast[b * H_ + tid] = rrelu(s + bq[tid]);
        }
    }
}

// ---------------------------------------------------------------------------
// fused: per (split, batch) block — ONE 64-token tile, 128 threads.
// Warps 0-1: K cols (rows 0-31 / 32-63); warps 2-3: V cols (same rows).
// Inner per-warp geometry identical to R12; 4 blocks/SM.
// ---------------------------------------------------------------------------
__global__ void __launch_bounds__(TPB, 4)
fused_attn(const float* __restrict__ ts, const float* __restrict__ seq,
           const int* __restrict__ lengths,
           const float* __restrict__ bk, const float* __restrict__ bv,
           float* __restrict__ out) {
    int b   = blockIdx.y;
    int sp  = blockIdx.x;
    int len = lengths[b];
    int start = sp * TILE_M;
    int tid = threadIdx.x;
    int wid = tid >> 5, lane = tid & 31;
    int idx = b * NSPLIT + sp;
    int nlive = min(NSPLIT, (len + TILE_M - 1) >> 6);

    if (sp >= nlive) return;   // dead split

    extern __shared__ char smem[];
    uint32_t sb = smem_u32(smem);
    float* sQ      = (float*)smem;             // 64
    float* sBias   = (float*)(smem + 256);     // 128
    float* sScore  = (float*)(smem + 768);     // 64
    float* sRed    = (float*)(smem + 1024);    // 2 x 64
    int*   sLast   = (int*)(smem + 1536);

    // ---- header loads: bias + q ----
    if (tid < DIN) sBias[tid] = (tid < H_) ? bk[tid] : bv[tid - H_];
    if (tid < H_)  sQ[tid] = g_qlast[b * H_ + tid];

    // ---- X tile: fp32 -> fp16, swizzled (64 rows x 16 chunks) ----
#pragma unroll
    for (int it = 0; it < 8; ++it) {
        int j = tid + it * TPB;               // 0..1023
        int row = j >> 4, ch = j & 15;
        int token = start + row;
        const float* src = (ch == 0)
            ? (ts + ((size_t)b * L_ + token) * DTS)
            : (seq + ((size_t)b * L_ + token) * DSEQ + (ch * 8 - 8));
        float4 f0 = ((const float4*)src)[0];
        float4 f1 = ((const float4*)src)[1];
        uint4 v = make_uint4(cvt_h2(f0.x, f0.y), cvt_h2(f0.z, f0.w),
                             cvt_h2(f1.x, f1.y), cvt_h2(f1.z, f1.w));
        uint32_t off = (uint32_t)(row * 256 + ((ch ^ (row & 7)) << 4));
        *(uint4*)(smem + XH_OFF + off) = v;
    }
    __syncthreads();

    int kw = wid & 1;                 // row group (rows kw*32 .. +32)
    int isV = wid >> 1;               // 0 = K cols (0-63), 1 = V cols (64-127)

    int li = lane >> 3, lr = lane & 7;
    int roff = ((li & 1) << 3) + lr;
    int ci   = li >> 1;
    int rm   = roff & 7;
    int g = lane >> 2, t = lane & 3;
    int t2 = 2 * t;

    const uint4* bf = g_Bfrag + (isV * 4) * 32 + lane;

    uint32_t a_row0 = sb + XH_OFF + (uint32_t)((kw * 32 + roff) * 256);
    uint32_t a_row1 = a_row0 + 16 * 256;

    float acc[2][8][4];
#pragma unroll
    for (int ms = 0; ms < 2; ++ms)
#pragma unroll
        for (int n = 0; n < 8; ++n)
#pragma unroll
            for (int i = 0; i < 4; ++i) acc[ms][n][i] = 0.f;

#pragma unroll
    for (int ks = 0; ks < 8; ++ks) {
        uint32_t aoff = ((uint32_t)((2 * ks + ci) ^ rm)) << 4;
        uint32_t a00, a01, a02, a03, a10, a11, a12, a13;
        LDSM_X4(a00, a01, a02, a03, a_row0 + aoff);
        LDSM_X4(a10, a11, a12, a13, a_row1 + aoff);
#pragma unroll
        for (int ntp = 0; ntp < 4; ++ntp) {
            uint4 f = bf[(ks * 8 + ntp) * 32];
            mma_f16(acc[0][2 * ntp],     a00, a01, a02, a03, f.x, f.y);
            mma_f16(acc[0][2 * ntp + 1], a00, a01, a02, a03, f.z, f.w);
            mma_f16(acc[1][2 * ntp],     a10, a11, a12, a13, f.x, f.y);
            mma_f16(acc[1][2 * ntp + 1], a10, a11, a12, a13, f.z, f.w);
        }
    }

    // ---- K warps: scores for their 32 rows ----
    if (!isV) {
#pragma unroll
        for (int ms = 0; ms < 2; ++ms) {
            float s0 = 0.f, s1 = 0.f;
#pragma unroll
            for (int nt = 0; nt < 8; ++nt) {
                int c0 = 8 * nt + t2, c1 = c0 + 1;
                float q0 = sQ[c0], q1 = sQ[c1];
                float b0 = sBias[c0], b1 = sBias[c1];
                s0 += q0 * rrelu(acc[ms][nt][0] + b0) + q1 * rrelu(acc[ms][nt][1] + b1);
                s1 += q0 * rrelu(acc[ms][nt][2] + b0) + q1 * rrelu(acc[ms][nt][3] + b1);
            }
            s0 += __shfl_xor_sync(0xffffffffu, s0, 1);
            s0 += __shfl_xor_sync(0xffffffffu, s0, 2);
            s1 += __shfl_xor_sync(0xffffffffu, s1, 1);
            s1 += __shfl_xor_sync(0xffffffffu, s1, 2);
            if (t == 0) {
                int r0 = kw * 32 + ms * 16 + g, r1 = r0 + 8;
                sScore[r0] = (start + r0 < len) ? s0 : -INFINITY;
                sScore[r1] = (start + r1 < len) ? s1 : -INFINITY;
            }
        }
    }
    __syncthreads();

    // ---- all-warp redundant softmax over 64 scores ----
    float mx, sum;
    {
        float v0 = sScore[lane], v1 = sScore[lane + 32];
        mx = fmaxf(v0, v1);
#pragma unroll
        for (int o = 16; o >= 1; o >>= 1)
            mx = fmaxf(mx, __shfl_xor_sync(0xffffffffu, mx, o));
        sum = __expf(v0 - mx) + __expf(v1 - mx);
#pragma unroll
        for (int o = 16; o >= 1; o >>= 1)
            sum += __shfl_xor_sync(0xffffffffu, sum, o);
    }

    // ---- V warps: weighted accumulate over their 32 rows ----
    if (isV) {
        int rb = kw * 32;
        float wa = __expf(sScore[rb + g]      - mx);
        float wb = __expf(sScore[rb + g + 8]  - mx);
        float wc = __expf(sScore[rb + g + 16] - mx);
        float wd = __expf(sScore[rb + g + 24] - mx);
#pragma unroll
        for (int nt = 0; nt < 8; ++nt) {
            int c0 = 8 * nt + t2, c1 = c0 + 1;
            float b0 = sBias[64 + c0], b1 = sBias[64 + c1];
            float p0 = wa * rrelu(acc[0][nt][0] + b0) + wb * rrelu(acc[0][nt][2] + b0)
                     + wc * rrelu(acc[1][nt][0] + b0) + wd * rrelu(acc[1][nt][2] + b0);
            float p1 = wa * rrelu(acc[0][nt][1] + b1) + wb * rrelu(acc[0][nt][3] + b1)
                     + wc * rrelu(acc[1][nt][1] + b1) + wd * rrelu(acc[1][nt][3] + b1);
            p0 += __shfl_xor_sync(0xffffffffu, p0, 4);
            p0 += __shfl_xor_sync(0xffffffffu, p0, 8);
            p0 += __shfl_xor_sync(0xffffffffu, p0, 16);
            p1 += __shfl_xor_sync(0xffffffffu, p1, 4);
            p1 += __shfl_xor_sync(0xffffffffu, p1, 8);
            p1 += __shfl_xor_sync(0xffffffffu, p1, 16);
            if (g == 0) {
                sRed[kw * 64 + c0] = p0;
                sRed[kw * 64 + c1] = p1;
            }
        }
    }
    __syncthreads();

    // ---- per-split partials ----
    if (tid < H_) {
        g_acc[idx * H_ + tid] = sRed[tid] + sRed[64 + tid];
    }
    if (tid == 0) { g_m[idx] = mx; g_s[idx] = sum; }

    // ---- last-block combine (threadfence reduction) ----
    __threadfence();
    __syncthreads();
    if (tid == 0) {
        int old = atomicAdd(&g_cnt[b], 1);
        *sLast = (old == nlive - 1);
    }
    __syncthreads();
    if (*sLast) {
        if (tid < H_) {
            volatile float* vm = g_m + b * NSPLIT;
            volatile float* vs = g_s + b * NSPLIT;
            volatile float* va = g_acc + (size_t)b * NSPLIT * H_;
            float MM = -INFINITY;
            for (int i = 0; i < nlive; ++i) MM = fmaxf(MM, vm[i]);
            float S = 0.f, A = 0.f;
            for (int i = 0; i < nlive; ++i) {
                float e = __expf(vm[i] - MM);
                S += vs[i] * e;
                A += va[i * H_ + tid] * e;
            }
            out[b * H_ + tid] = A / S;
        }
        if (tid == 0) g_cnt[b] = 0;   // reset for next replay
    }
}

// ---------------------------------------------------------------------------
extern "C" void kernel_launch(void* const* d_in, const int* in_sizes, int n_in,
                              void* d_out, int out_size) {
    const float* ts      = (const float*)d_in[0];
    const float* seq     = (const float*)d_in[1];
    const int*   lengths = (const int*)  d_in[2];
    const float* Wk      = (const float*)d_in[3];
    const float* bk      = (const float*)d_in[4];
    const float* Wq      = (const float*)d_in[5];
    const float* bq      = (const float*)d_in[6];
    const float* Wv      = (const float*)d_in[7];
    const float* bv      = (const float*)d_in[8];
    float* out = (float*)d_out;

    static int configured = 0;
    if (!configured) {
        cudaFuncSetAttribute(fused_attn,
                             cudaFuncAttributeMaxDynamicSharedMemorySize, SMEM_TOTAL);
        configured = 1;
    }

    prep_kernel<<<8 + B_, 256>>>(ts, seq, lengths, Wk, Wv, Wq, bq);
    dim3 grid(NSPLIT, B_);
    fused_attn<<<grid, TPB, SMEM_TOTAL>>>(ts, seq, lengths, bk, bv, out);
}